// round 15
// baseline (speedup 1.0000x reference)
#include <cuda_runtime.h>
#include <cuda_fp16.h>
#include <cstdint>

// Problem constants
#define B_SZ   256
#define T_SZ   2049
#define D_SZ   64
#define NI_SZ  128
#define OUT_SZ 10
#define L_SZ   2080
#define S_SZ   16
#define BN_TOT 32768          // GEMM M
#define NBP    8320           // GEMM N: 8192 (W2) + 64 (b2) + 64 zero
#define KD     2080           // GEMM K: 65 iters of 32
#define BM     128
#define BN     128
#define BK     32
#define NKIT   (KD / BK)      // 65
#define STAGE_B 32768         // A 16KB + B 16KB per stage
#define NT_TILES 65           // NBP / BN
#define MT_TILES 256          // BN_TOT / BM
#define GRP    16             // ntile group width for L2-aware rasterization

// Scratch (device globals; allocation-free)
__device__ __half g_ls_hi[(size_t)BN_TOT * KD];   // 136 MB
__device__ __half g_ls_lo[(size_t)BN_TOT * KD];   // 136 MB
__device__ __half g_B_hi [(size_t)NBP * KD];      // 34.6 MB
__device__ __half g_B_lo [(size_t)NBP * KD];      // 34.6 MB
__device__ float  g_V    [(size_t)BN_TOT * NBP];  // 1.09 GB

__device__ __forceinline__ void hsplit(float v, __half& h, __half& l) {
    h = __float2half_rn(v);
    l = __float2half_rn(v - __half2float(h));
}
__device__ __forceinline__ void cp16s(uint32_t saddr, const void* g) {
    asm volatile("cp.async.cg.shared.global [%0], [%1], 16;" :: "r"(saddr), "l"(g));
}

// ---------------------------------------------------------------------------
// Kernel 0: B rows = [W2 flat (8192); b2 (64); zeros (64)], fp16 hi/lo.
// ---------------------------------------------------------------------------
__global__ void prep_B_k(const float* __restrict__ W2, const float* __restrict__ b2) {
    int r = blockIdx.x;
    const float* src = nullptr;
    if (r < 8192)       src = W2 + (size_t)r * L_SZ;
    else if (r < 8256)  src = b2 + (size_t)(r - 8192) * L_SZ;
    size_t o = (size_t)r * KD;
    for (int l = threadIdx.x; l < KD; l += blockDim.x) {
        float v = src ? src[l] : 0.0f;
        __half h, lo;
        hsplit(v, h, lo);
        g_B_hi[o + l] = h;
        g_B_lo[o + l] = lo;
    }
}

// ---------------------------------------------------------------------------
// Kernel 1: depth-2 log-signature per (b, n), fp16 hi/lo output.
// ---------------------------------------------------------------------------
__global__ void logsig_k(const float* __restrict__ X) {
    __shared__ float seg[17 * 64];
    __shared__ float cumS[16 * 64];
    __shared__ float dltS[16 * 64];
    __shared__ float Ms[64 * 64];

    int n = blockIdx.x, b = blockIdx.y;
    size_t bno = (size_t)(b * NI_SZ + n) * KD;
    int t = threadIdx.x;

    const float4* xp4 = (const float4*)(X + ((size_t)b * T_SZ + (size_t)n * S_SZ) * D_SZ);
    float4* seg4 = (float4*)seg;
    for (int i = t; i < 17 * 64 / 4; i += 256) seg4[i] = xp4[i];
    __syncthreads();

    for (int i = t; i < 16 * 64; i += 256) {
        int k = i >> 6, d = i & 63;
        cumS[i] = seg[k * 64 + d] - seg[d];
        dltS[i] = seg[(k + 1) * 64 + d] - seg[k * 64 + d];
    }
    __syncthreads();

    if (t < 64) {
        __half h, lo;
        hsplit(seg[16 * 64 + t] - seg[t], h, lo);
        g_ls_hi[bno + t] = h; g_ls_lo[bno + t] = lo;
    }

    {
        int i = t >> 2;
        int jb = (t & 3) * 16;
        float acc[16];
        #pragma unroll
        for (int q = 0; q < 16; ++q) acc[q] = 0.0f;
        #pragma unroll
        for (int k = 0; k < 16; ++k) {
            float ci = cumS[k * 64 + i];
            const float4* dl4 = (const float4*)(dltS + k * 64 + jb);
            #pragma unroll
            for (int q4 = 0; q4 < 4; ++q4) {
                float4 dv = dl4[q4];
                acc[q4 * 4 + 0] += ci * dv.x;
                acc[q4 * 4 + 1] += ci * dv.y;
                acc[q4 * 4 + 2] += ci * dv.z;
                acc[q4 * 4 + 3] += ci * dv.w;
            }
        }
        float4* mrow = (float4*)(Ms + i * 64 + jb);
        #pragma unroll
        for (int q4 = 0; q4 < 4; ++q4)
            mrow[q4] = make_float4(acc[q4 * 4 + 0], acc[q4 * 4 + 1],
                                   acc[q4 * 4 + 2], acc[q4 * 4 + 3]);
    }
    __syncthreads();

    for (int p = t; p < 2016; p += 256) {
        int i = 0, rs = 0;
        while (rs + (63 - i) <= p) { rs += 63 - i; ++i; }
        int j = i + 1 + (p - rs);
        float a = 0.5f * (Ms[i * 64 + j] - Ms[j * 64 + i]);
        __half h, lo;
        hsplit(a, h, lo);
        g_ls_hi[bno + 64 + p] = h; g_ls_lo[bno + 64 + p] = lo;
    }
}

// ---------------------------------------------------------------------------
// Kernel 2: TN GEMM  g_V = ls @ B^T, m16n8k16.f16 fp32-acc, 3-product split.
// Round-9 proven body; ONLY change: L2-aware rasterization — 1D grid decoded
// in ntile-groups of 16 so each wave's B working set (~17MB) stays L2-warm.
// ---------------------------------------------------------------------------
__device__ __forceinline__ void ldsm4(uint32_t* r, uint32_t addr) {
    asm volatile("ldmatrix.sync.aligned.m8n8.x4.shared.b16 {%0,%1,%2,%3}, [%4];"
                 : "=r"(r[0]), "=r"(r[1]), "=r"(r[2]), "=r"(r[3]) : "r"(addr));
}
__device__ __forceinline__ void mma_f16(float* c, const uint32_t* a, const uint32_t* b) {
    asm volatile(
        "mma.sync.aligned.m16n8k16.row.col.f32.f16.f16.f32 "
        "{%0,%1,%2,%3}, {%4,%5,%6,%7}, {%8,%9}, {%0,%1,%2,%3};"
        : "+f"(c[0]), "+f"(c[1]), "+f"(c[2]), "+f"(c[3])
        : "r"(a[0]), "r"(a[1]), "r"(a[2]), "r"(a[3]), "r"(b[0]), "r"(b[1]));
}

__global__ void __launch_bounds__(256, 2) gemm_k() {
    extern __shared__ uint8_t dsm_raw[];
    uint32_t base0 = (uint32_t)__cvta_generic_to_shared(dsm_raw);
    uint32_t sbase = (base0 + 1023) & ~1023u;

    int tid  = threadIdx.x;
    int lane = tid & 31;
    int wid  = tid >> 5;
    int g    = lane >> 2;
    int tig  = lane & 3;
    int wm   = (wid & 1) * 64;
    int wn   = (wid >> 1) * 32;

    // L2-aware decode: groups of GRP ntiles; within a group, mtile varies
    // fastest so a wave covers ~9 mtiles x 16 ntiles (working set ~28MB).
    int idx = blockIdx.x;
    int gp  = idx / (GRP * MT_TILES);
    int rem = idx - gp * (GRP * MT_TILES);
    int gw  = min(GRP, NT_TILES - gp * GRP);
    int mtile = rem / gw;
    int ntile = gp * GRP + (rem - mtile * gw);

    const __half* Agh = g_ls_hi + (size_t)(mtile * BM) * KD;
    const __half* Agl = g_ls_lo + (size_t)(mtile * BM) * KD;
    const __half* Bgh = g_B_hi  + (size_t)(ntile * BN) * KD;
    const __half* Bgl = g_B_lo  + (size_t)(ntile * BN) * KD;

    float c[4][4][4];
    #pragma unroll
    for (int mi = 0; mi < 4; ++mi)
        #pragma unroll
        for (int ni = 0; ni < 4; ++ni)
            #pragma unroll
            for (int q = 0; q < 4; ++q) c[mi][ni][q] = 0.0f;

    // Stage: A 128 rows + B 128 rows, each row 128B = [hi 64B | lo 64B]
    auto stage = [&](int it2, int s) {
        uint32_t base = sbase + (uint32_t)s * STAGE_B;
        int kb = it2 * BK;
        #pragma unroll
        for (int i = 0; i < 8; ++i) {
            int isB   = (i >= 4);
            int local = tid + i * 256 - isB * 1024;
            int row   = local >> 3;
            int ch    = local & 7;
            int hil   = ch >> 2;
            int ck    = ch & 3;
            const __half* src =
                (isB ? (hil ? Bgl : Bgh) + (size_t)row * KD
                     : (hil ? Agl : Agh) + (size_t)row * KD) + kb + ck * 8;
            uint32_t dst = base + (isB ? 16384u : 0u)
                         + (uint32_t)row * 128 + (uint32_t)((ch ^ (row & 7)) << 4);
            cp16s(dst, src);
        }
        asm volatile("cp.async.commit_group;");
    };

    stage(0, 0);

    for (int it = 0; it < NKIT; ++it) {
        int s = it & 1;
        if (it + 1 < NKIT) {
            stage(it + 1, s ^ 1);
            asm volatile("cp.async.wait_group 1;");
        } else {
            asm volatile("cp.async.wait_group 0;");
        }
        __syncthreads();

        uint32_t Ab = sbase + (uint32_t)s * STAGE_B;
        uint32_t Bb = Ab + 16384;

        #pragma unroll
        for (int ks = 0; ks < 2; ++ks) {
            uint32_t ah[4][4], al[4][4], bh[4][2], bl[4][2];
            #pragma unroll
            for (int mi = 0; mi < 4; ++mi) {
                int row = wm + mi * 16 + (lane & 15);
                int kc  = lane >> 4;
                ldsm4(ah[mi], Ab + row * 128 + (((ks * 2 + kc)     ^ (row & 7)) << 4));
                ldsm4(al[mi], Ab + row * 128 + (((4 + ks * 2 + kc) ^ (row & 7)) << 4));
            }
            #pragma unroll
            for (int p = 0; p < 2; ++p) {
                int row = wn + p * 16 + ((lane >> 4) & 1) * 8 + (lane & 7);
                int kc  = (lane >> 3) & 1;
                uint32_t r4[4];
                ldsm4(r4, Bb + row * 128 + (((ks * 2 + kc) ^ (row & 7)) << 4));
                bh[2*p][0] = r4[0]; bh[2*p][1] = r4[1];
                bh[2*p+1][0] = r4[2]; bh[2*p+1][1] = r4[3];
                ldsm4(r4, Bb + row * 128 + (((4 + ks * 2 + kc) ^ (row & 7)) << 4));
                bl[2*p][0] = r4[0]; bl[2*p][1] = r4[1];
                bl[2*p+1][0] = r4[2]; bl[2*p+1][1] = r4[3];
            }
            #pragma unroll
            for (int mi = 0; mi < 4; ++mi)
                #pragma unroll
                for (int ni = 0; ni < 4; ++ni) {
                    mma_f16(c[mi][ni], al[mi], bh[ni]);
                    mma_f16(c[mi][ni], ah[mi], bl[ni]);
                    mma_f16(c[mi][ni], ah[mi], bh[ni]);
                }
        }
        __syncthreads();   // REQUIRED: protects buffer s^1 from next-iter staging
    }

    // Epilogue
    int rowbase = mtile * BM + wm;
    int colbase = ntile * BN + wn;
    #pragma unroll
    for (int mi = 0; mi < 4; ++mi) {
        #pragma unroll
        for (int ni = 0; ni < 4; ++ni) {
            int r0 = rowbase + mi * 16 + g;
            int cc = colbase + ni * 8 + tig * 2;
            *(float2*)&g_V[(size_t)r0 * NBP + cc] =
                make_float2(c[mi][ni][0], c[mi][ni][1]);
            *(float2*)&g_V[(size_t)(r0 + 8) * NBP + cc] =
                make_float2(c[mi][ni][2], c[mi][ni][3]);
        }
    }
}

// ---------------------------------------------------------------------------
// Kernel 3: RK4 scan. 128 CTAs x 256 threads; 2 batch elems per CTA;
// cp.async double-buffered V prefetch (round-9 proven); k-dot split across
// both 64-thread segments (2 threads per d, 64 m each) + pair reduction.
// ---------------------------------------------------------------------------
#define VSLC 8256   // 129*64 floats per interval slice

__device__ __forceinline__ void hbar(int half) {
    asm volatile("bar.sync %0, 128;" :: "r"(half + 1) : "memory");
}

__global__ void __launch_bounds__(256) scan_k(
    const float* __restrict__ X,    const float* __restrict__ W_in,
    const float* __restrict__ b_in, const float* __restrict__ W1,
    const float* __restrict__ b1,   const float* __restrict__ W_out,
    const float* __restrict__ b_out, float* __restrict__ out)
{
    extern __shared__ float ssm[];
    float* VsA  = ssm;
    float* hA   = ssm + 4 * VSLC;
    float* htA  = hA + 128;
    float* zA   = htA + 128;
    float* ksA  = zA + 256;
    float* prtA = ksA + 128;   // 2 x 128 partials

    int half = threadIdx.x >> 7;
    int t    = threadIdx.x & 127;
    int b    = blockIdx.x * 2 + half;

    float* h    = hA   + half * 64;
    float* ht   = htA  + half * 64;
    float* z    = zA   + half * 128;
    float* ksum = ksA  + half * 64;
    float* part = prtA + half * 128;

    float w1r[64];
    #pragma unroll
    for (int i = 0; i < 64; ++i) w1r[i] = W1[i * 128 + t];
    float b1t = b1[t];

    if (t < 64) {
        float acc = b_in[t];
        const float* x0 = X + (size_t)b * T_SZ * D_SZ;
        #pragma unroll
        for (int d = 0; d < 64; ++d) acc += x0[d] * W_in[d * 64 + t];
        h[t] = acc; ht[t] = acc; ksum[t] = 0.0f;
    }

    uint32_t vs_s[2];
    vs_s[0] = (uint32_t)__cvta_generic_to_shared(VsA + (half * 2 + 0) * VSLC);
    vs_s[1] = (uint32_t)__cvta_generic_to_shared(VsA + (half * 2 + 1) * VSLC);

    auto prefetch = [&](int n, int buf) {
        const float* vg = g_V + (size_t)(b * NI_SZ + n) * NBP;
        uint32_t dst = vs_s[buf];
        for (int c4 = t; c4 < VSLC / 4; c4 += 128)
            cp16s(dst + c4 * 16, vg + c4 * 4);
        asm volatile("cp.async.commit_group;");
    };

    prefetch(0, 0);

    const float wgt[4] = {1.0f, 2.0f, 2.0f, 1.0f};
    const float aco[4] = {0.5f, 0.5f, 1.0f, 0.0f};

    int d   = t & 63;
    int sg  = t >> 6;          // 0 or 1: m-range segment
    int m0  = sg * 64;

    for (int n = 0; n < NI_SZ; ++n) {
        asm volatile("cp.async.wait_group 0;");
        hbar(half);
        if (n + 1 < NI_SZ) prefetch(n + 1, (n + 1) & 1);
        const float* Vs = VsA + (half * 2 + (n & 1)) * VSLC;

        #pragma unroll
        for (int s = 0; s < 4; ++s) {
            float a0 = b1t, a1 = 0.0f, a2 = 0.0f, a3 = 0.0f;
            #pragma unroll
            for (int i = 0; i < 64; i += 4) {
                a0 += ht[i]     * w1r[i];
                a1 += ht[i + 1] * w1r[i + 1];
                a2 += ht[i + 2] * w1r[i + 2];
                a3 += ht[i + 3] * w1r[i + 3];
            }
            z[t] = tanhf((a0 + a1) + (a2 + a3));
            hbar(half);
            {   // split k-dot: this thread covers m in [m0, m0+64)
                float k0 = (sg == 0) ? Vs[128 * 64 + d] : 0.0f;
                float k1 = 0.0f, k2 = 0.0f, k3 = 0.0f;
                const float* vp = Vs + m0 * 64 + d;
                const float* zp = z + m0;
                #pragma unroll
                for (int m = 0; m < 64; m += 4) {
                    k0 += zp[m]     * vp[m * 64];
                    k1 += zp[m + 1] * vp[(m + 1) * 64];
                    k2 += zp[m + 2] * vp[(m + 2) * 64];
                    k3 += zp[m + 3] * vp[(m + 3) * 64];
                }
                part[t] = (k0 + k1) + (k2 + k3);
            }
            hbar(half);
            if (t < 64) {
                float ka = part[t] + part[64 + t];
                ksum[t] += wgt[s] * ka;
                if (s < 3) ht[t] = h[t] + aco[s] * ka;
            }
            hbar(half);
        }
        if (t < 64) {
            float hn = h[t] + ksum[t] * (1.0f / 6.0f);
            h[t] = hn; ht[t] = hn; ksum[t] = 0.0f;
        }
    }

    if (t < OUT_SZ) {
        float acc = b_out[t];
        #pragma unroll
        for (int dd = 0; dd < 64; ++dd) acc += h[dd] * W_out[dd * OUT_SZ + t];
        out[b * OUT_SZ + t] = acc;
    }
}

// ---------------------------------------------------------------------------
extern "C" void kernel_launch(void* const* d_in, const int* in_sizes, int n_in,
                              void* d_out, int out_size) {
    const float* X     = (const float*)d_in[0];
    const float* W_in  = (const float*)d_in[1];
    const float* b_in  = (const float*)d_in[2];
    const float* W1    = (const float*)d_in[3];
    const float* b1    = (const float*)d_in[4];
    const float* W2    = (const float*)d_in[5];
    const float* b2    = (const float*)d_in[6];
    const float* W_out = (const float*)d_in[7];
    const float* b_out = (const float*)d_in[8];
    float* out = (float*)d_out;

    (void)in_sizes; (void)n_in; (void)out_size;

    int gemm_smem = 2 * STAGE_B + 1024;                             // 66560
    cudaFuncSetAttribute(gemm_k, cudaFuncAttributeMaxDynamicSharedMemorySize, gemm_smem);
    int scan_smem = (4 * VSLC + 128 + 128 + 256 + 128 + 256) * 4;   // 135680
    cudaFuncSetAttribute(scan_k, cudaFuncAttributeMaxDynamicSharedMemorySize, scan_smem);

    prep_B_k<<<NBP, 128>>>(W2, b2);
    logsig_k<<<dim3(NI_SZ, B_SZ), 256>>>(X);
    gemm_k<<<NT_TILES * MT_TILES, 256, gemm_smem>>>();
    scan_k<<<B_SZ / 2, 256, scan_smem>>>(X, W_in, b_in, W1, b1, W_out, b_out, out);
}

// round 16
// speedup vs baseline: 1.5552x; 1.5552x over previous
#include <cuda_runtime.h>
#include <cuda_fp16.h>
#include <cstdint>

// Problem constants
#define B_SZ   256
#define T_SZ   2049
#define D_SZ   64
#define NI_SZ  128
#define OUT_SZ 10
#define L_SZ   2080
#define S_SZ   16
#define BN_TOT 32768          // GEMM M
#define NBP    8320           // GEMM N: 8192 (W2) + 64 (b2) + 64 zero
#define KD     2080           // GEMM K: 65 iters of 32
#define BM     128
#define BN     128
#define BK     32
#define NKIT   (KD / BK)      // 65
#define STAGE_B 32768         // A 16KB + B 16KB per stage

// Scratch (device globals; allocation-free)
__device__ __half g_ls_hi[(size_t)BN_TOT * KD];   // 136 MB
__device__ __half g_ls_lo[(size_t)BN_TOT * KD];   // 136 MB
__device__ __half g_B_hi [(size_t)NBP * KD];      // 34.6 MB
__device__ __half g_B_lo [(size_t)NBP * KD];      // 34.6 MB
__device__ float  g_V    [(size_t)BN_TOT * NBP];  // 1.09 GB

__device__ __forceinline__ void hsplit(float v, __half& h, __half& l) {
    h = __float2half_rn(v);
    l = __float2half_rn(v - __half2float(h));
}
__device__ __forceinline__ void cp16s(uint32_t saddr, const void* g) {
    asm volatile("cp.async.cg.shared.global [%0], [%1], 16;" :: "r"(saddr), "l"(g));
}

// ---------------------------------------------------------------------------
// Kernel 1 (fused): blocks [0, 32768) compute the depth-2 log-signature for
// (b, n); blocks [32768, 41088) build B rows = [W2 flat; b2; zeros].
// The two halves are independent; fusing removes prep_B's serial tail.
// ---------------------------------------------------------------------------
__global__ void prep_all_k(const float* __restrict__ X,
                           const float* __restrict__ W2,
                           const float* __restrict__ b2) {
    __shared__ float seg[17 * 64];
    __shared__ float cumS[16 * 64];
    __shared__ float dltS[16 * 64];
    __shared__ float Ms[64 * 64];

    int t = threadIdx.x;

    if (blockIdx.x >= (unsigned)BN_TOT) {        // ---- prep_B half ----
        int r = blockIdx.x - BN_TOT;
        const float* src = nullptr;
        if (r < 8192)       src = W2 + (size_t)r * L_SZ;
        else if (r < 8256)  src = b2 + (size_t)(r - 8192) * L_SZ;
        size_t o = (size_t)r * KD;
        for (int l = t; l < KD; l += 256) {
            float v = src ? src[l] : 0.0f;
            __half h, lo;
            hsplit(v, h, lo);
            g_B_hi[o + l] = h;
            g_B_lo[o + l] = lo;
        }
        return;
    }

    // ---- logsig half ----
    int n = blockIdx.x & (NI_SZ - 1);
    int b = blockIdx.x >> 7;
    size_t bno = (size_t)(b * NI_SZ + n) * KD;

    const float4* xp4 = (const float4*)(X + ((size_t)b * T_SZ + (size_t)n * S_SZ) * D_SZ);
    float4* seg4 = (float4*)seg;
    for (int i = t; i < 17 * 64 / 4; i += 256) seg4[i] = xp4[i];
    __syncthreads();

    for (int i = t; i < 16 * 64; i += 256) {
        int k = i >> 6, d = i & 63;
        cumS[i] = seg[k * 64 + d] - seg[d];
        dltS[i] = seg[(k + 1) * 64 + d] - seg[k * 64 + d];
    }
    __syncthreads();

    if (t < 64) {
        __half h, lo;
        hsplit(seg[16 * 64 + t] - seg[t], h, lo);
        g_ls_hi[bno + t] = h; g_ls_lo[bno + t] = lo;
    }

    {
        int i = t >> 2;
        int jb = (t & 3) * 16;
        float acc[16];
        #pragma unroll
        for (int q = 0; q < 16; ++q) acc[q] = 0.0f;
        #pragma unroll
        for (int k = 0; k < 16; ++k) {
            float ci = cumS[k * 64 + i];
            const float4* dl4 = (const float4*)(dltS + k * 64 + jb);
            #pragma unroll
            for (int q4 = 0; q4 < 4; ++q4) {
                float4 dv = dl4[q4];
                acc[q4 * 4 + 0] += ci * dv.x;
                acc[q4 * 4 + 1] += ci * dv.y;
                acc[q4 * 4 + 2] += ci * dv.z;
                acc[q4 * 4 + 3] += ci * dv.w;
            }
        }
        float4* mrow = (float4*)(Ms + i * 64 + jb);
        #pragma unroll
        for (int q4 = 0; q4 < 4; ++q4)
            mrow[q4] = make_float4(acc[q4 * 4 + 0], acc[q4 * 4 + 1],
                                   acc[q4 * 4 + 2], acc[q4 * 4 + 3]);
    }
    __syncthreads();

    for (int p = t; p < 2016; p += 256) {
        int i = 0, rs = 0;
        while (rs + (63 - i) <= p) { rs += 63 - i; ++i; }
        int j = i + 1 + (p - rs);
        float a = 0.5f * (Ms[i * 64 + j] - Ms[j * 64 + i]);
        __half h, lo;
        hsplit(a, h, lo);
        g_ls_hi[bno + 64 + p] = h; g_ls_lo[bno + 64 + p] = lo;
    }
}

// ---------------------------------------------------------------------------
// Kernel 2: TN GEMM  g_V = ls @ B^T, m16n8k16.f16 fp32-acc, 3-product split
// (al*bh + ah*bl + ah*bh). CTA 128x128x32, 8 warps (2x4), warp 64x32,
// 2-stage cp.async with trailing barrier; 2 CTAs/SM. (Round-9 proven body.)
// ---------------------------------------------------------------------------
__device__ __forceinline__ void ldsm4(uint32_t* r, uint32_t addr) {
    asm volatile("ldmatrix.sync.aligned.m8n8.x4.shared.b16 {%0,%1,%2,%3}, [%4];"
                 : "=r"(r[0]), "=r"(r[1]), "=r"(r[2]), "=r"(r[3]) : "r"(addr));
}
__device__ __forceinline__ void mma_f16(float* c, const uint32_t* a, const uint32_t* b) {
    asm volatile(
        "mma.sync.aligned.m16n8k16.row.col.f32.f16.f16.f32 "
        "{%0,%1,%2,%3}, {%4,%5,%6,%7}, {%8,%9}, {%0,%1,%2,%3};"
        : "+f"(c[0]), "+f"(c[1]), "+f"(c[2]), "+f"(c[3])
        : "r"(a[0]), "r"(a[1]), "r"(a[2]), "r"(a[3]), "r"(b[0]), "r"(b[1]));
}

__global__ void __launch_bounds__(256, 2) gemm_k() {
    extern __shared__ uint8_t dsm_raw[];
    uint32_t base0 = (uint32_t)__cvta_generic_to_shared(dsm_raw);
    uint32_t sbase = (base0 + 1023) & ~1023u;

    int tid  = threadIdx.x;
    int lane = tid & 31;
    int wid  = tid >> 5;
    int g    = lane >> 2;
    int tig  = lane & 3;
    int wm   = (wid & 1) * 64;
    int wn   = (wid >> 1) * 32;
    int ntile = blockIdx.x, mtile = blockIdx.y;

    const __half* Agh = g_ls_hi + (size_t)(mtile * BM) * KD;
    const __half* Agl = g_ls_lo + (size_t)(mtile * BM) * KD;
    const __half* Bgh = g_B_hi  + (size_t)(ntile * BN) * KD;
    const __half* Bgl = g_B_lo  + (size_t)(ntile * BN) * KD;

    float c[4][4][4];
    #pragma unroll
    for (int mi = 0; mi < 4; ++mi)
        #pragma unroll
        for (int ni = 0; ni < 4; ++ni)
            #pragma unroll
            for (int q = 0; q < 4; ++q) c[mi][ni][q] = 0.0f;

    // Stage: A 128 rows + B 128 rows, each row 128B = [hi 64B | lo 64B]
    auto stage = [&](int it2, int s) {
        uint32_t base = sbase + (uint32_t)s * STAGE_B;
        int kb = it2 * BK;
        #pragma unroll
        for (int i = 0; i < 8; ++i) {
            int isB   = (i >= 4);
            int local = tid + i * 256 - isB * 1024;
            int row   = local >> 3;
            int ch    = local & 7;
            int hil   = ch >> 2;
            int ck    = ch & 3;
            const __half* src =
                (isB ? (hil ? Bgl : Bgh) + (size_t)row * KD
                     : (hil ? Agl : Agh) + (size_t)row * KD) + kb + ck * 8;
            uint32_t dst = base + (isB ? 16384u : 0u)
                         + (uint32_t)row * 128 + (uint32_t)((ch ^ (row & 7)) << 4);
            cp16s(dst, src);
        }
        asm volatile("cp.async.commit_group;");
    };

    stage(0, 0);

    for (int it = 0; it < NKIT; ++it) {
        int s = it & 1;
        if (it + 1 < NKIT) {
            stage(it + 1, s ^ 1);
            asm volatile("cp.async.wait_group 1;");
        } else {
            asm volatile("cp.async.wait_group 0;");
        }
        __syncthreads();

        uint32_t Ab = sbase + (uint32_t)s * STAGE_B;
        uint32_t Bb = Ab + 16384;

        #pragma unroll
        for (int ks = 0; ks < 2; ++ks) {
            uint32_t ah[4][4], al[4][4], bh[4][2], bl[4][2];
            #pragma unroll
            for (int mi = 0; mi < 4; ++mi) {
                int row = wm + mi * 16 + (lane & 15);
                int kc  = lane >> 4;
                ldsm4(ah[mi], Ab + row * 128 + (((ks * 2 + kc)     ^ (row & 7)) << 4));
                ldsm4(al[mi], Ab + row * 128 + (((4 + ks * 2 + kc) ^ (row & 7)) << 4));
            }
            #pragma unroll
            for (int p = 0; p < 2; ++p) {
                int row = wn + p * 16 + ((lane >> 4) & 1) * 8 + (lane & 7);
                int kc  = (lane >> 3) & 1;
                uint32_t r4[4];
                ldsm4(r4, Bb + row * 128 + (((ks * 2 + kc) ^ (row & 7)) << 4));
                bh[2*p][0] = r4[0]; bh[2*p][1] = r4[1];
                bh[2*p+1][0] = r4[2]; bh[2*p+1][1] = r4[3];
                ldsm4(r4, Bb + row * 128 + (((4 + ks * 2 + kc) ^ (row & 7)) << 4));
                bl[2*p][0] = r4[0]; bl[2*p][1] = r4[1];
                bl[2*p+1][0] = r4[2]; bl[2*p+1][1] = r4[3];
            }
            #pragma unroll
            for (int mi = 0; mi < 4; ++mi)
                #pragma unroll
                for (int ni = 0; ni < 4; ++ni) {
                    mma_f16(c[mi][ni], al[mi], bh[ni]);
                    mma_f16(c[mi][ni], ah[mi], bl[ni]);
                    mma_f16(c[mi][ni], ah[mi], bh[ni]);
                }
        }
        __syncthreads();   // REQUIRED: protects buffer s^1 from next-iter staging
    }

    // Epilogue
    int rowbase = mtile * BM + wm;
    int colbase = ntile * BN + wn;
    #pragma unroll
    for (int mi = 0; mi < 4; ++mi) {
        #pragma unroll
        for (int ni = 0; ni < 4; ++ni) {
            int r0 = rowbase + mi * 16 + g;
            int cc = colbase + ni * 8 + tig * 2;
            *(float2*)&g_V[(size_t)r0 * NBP + cc] =
                make_float2(c[mi][ni][0], c[mi][ni][1]);
            *(float2*)&g_V[(size_t)(r0 + 8) * NBP + cc] =
                make_float2(c[mi][ni][2], c[mi][ni][3]);
        }
    }
}

// ---------------------------------------------------------------------------
// Kernel 3: RK4 scan. 128 CTAs x 256 threads; 2 batch elems per CTA;
// cp.async double-buffered V prefetch; per-half named barriers.
// (Round-9 proven body, 563us.)
// ---------------------------------------------------------------------------
#define VSLC 8256   // 129*64 floats per interval slice

__device__ __forceinline__ void hbar(int half) {
    asm volatile("bar.sync %0, 128;" :: "r"(half + 1) : "memory");
}

__global__ void __launch_bounds__(256) scan_k(
    const float* __restrict__ X,    const float* __restrict__ W_in,
    const float* __restrict__ b_in, const float* __restrict__ W1,
    const float* __restrict__ b1,   const float* __restrict__ W_out,
    const float* __restrict__ b_out, float* __restrict__ out)
{
    extern __shared__ float ssm[];
    float* VsA = ssm;
    float* hA  = ssm + 4 * VSLC;
    float* htA = hA + 128;
    float* zA  = htA + 128;
    float* ksA = zA + 256;

    int half = threadIdx.x >> 7;
    int t    = threadIdx.x & 127;
    int b    = blockIdx.x * 2 + half;

    float* h    = hA  + half * 64;
    float* ht   = htA + half * 64;
    float* z    = zA  + half * 128;
    float* ksum = ksA + half * 64;

    float w1r[64];
    #pragma unroll
    for (int i = 0; i < 64; ++i) w1r[i] = W1[i * 128 + t];
    float b1t = b1[t];

    if (t < 64) {
        float acc = b_in[t];
        const float* x0 = X + (size_t)b * T_SZ * D_SZ;
        #pragma unroll
        for (int d = 0; d < 64; ++d) acc += x0[d] * W_in[d * 64 + t];
        h[t] = acc; ht[t] = acc; ksum[t] = 0.0f;
    }

    uint32_t vs_s[2];
    vs_s[0] = (uint32_t)__cvta_generic_to_shared(VsA + (half * 2 + 0) * VSLC);
    vs_s[1] = (uint32_t)__cvta_generic_to_shared(VsA + (half * 2 + 1) * VSLC);

    auto prefetch = [&](int n, int buf) {
        const float* vg = g_V + (size_t)(b * NI_SZ + n) * NBP;
        uint32_t dst = vs_s[buf];
        for (int c4 = t; c4 < VSLC / 4; c4 += 128)
            cp16s(dst + c4 * 16, vg + c4 * 4);
        asm volatile("cp.async.commit_group;");
    };

    prefetch(0, 0);

    const float wgt[4] = {1.0f, 2.0f, 2.0f, 1.0f};
    const float aco[4] = {0.5f, 0.5f, 1.0f, 0.0f};

    for (int n = 0; n < NI_SZ; ++n) {
        asm volatile("cp.async.wait_group 0;");
        hbar(half);
        if (n + 1 < NI_SZ) prefetch(n + 1, (n + 1) & 1);
        const float* Vs = VsA + (half * 2 + (n & 1)) * VSLC;

        #pragma unroll
        for (int s = 0; s < 4; ++s) {
            float a0 = b1t, a1 = 0.0f, a2 = 0.0f, a3 = 0.0f;
            #pragma unroll
            for (int i = 0; i < 64; i += 4) {
                a0 += ht[i]     * w1r[i];
                a1 += ht[i + 1] * w1r[i + 1];
                a2 += ht[i + 2] * w1r[i + 2];
                a3 += ht[i + 3] * w1r[i + 3];
            }
            z[t] = tanhf((a0 + a1) + (a2 + a3));
            hbar(half);
            if (t < 64) {
                float k0 = Vs[128 * 64 + t], k1 = 0.0f, k2 = 0.0f, k3 = 0.0f;
                #pragma unroll
                for (int m = 0; m < 128; m += 4) {
                    k0 += z[m]     * Vs[m * 64 + t];
                    k1 += z[m + 1] * Vs[(m + 1) * 64 + t];
                    k2 += z[m + 2] * Vs[(m + 2) * 64 + t];
                    k3 += z[m + 3] * Vs[(m + 3) * 64 + t];
                }
                float ka = (k0 + k1) + (k2 + k3);
                ksum[t] += wgt[s] * ka;
                if (s < 3) ht[t] = h[t] + aco[s] * ka;
            }
            hbar(half);
        }
        if (t < 64) {
            float hn = h[t] + ksum[t] * (1.0f / 6.0f);
            h[t] = hn; ht[t] = hn; ksum[t] = 0.0f;
        }
    }

    if (t < OUT_SZ) {
        float acc = b_out[t];
        #pragma unroll
        for (int d = 0; d < 64; ++d) acc += h[d] * W_out[d * OUT_SZ + t];
        out[b * OUT_SZ + t] = acc;
    }
}

// ---------------------------------------------------------------------------
extern "C" void kernel_launch(void* const* d_in, const int* in_sizes, int n_in,
                              void* d_out, int out_size) {
    const float* X     = (const float*)d_in[0];
    const float* W_in  = (const float*)d_in[1];
    const float* b_in  = (const float*)d_in[2];
    const float* W1    = (const float*)d_in[3];
    const float* b1    = (const float*)d_in[4];
    const float* W2    = (const float*)d_in[5];
    const float* b2    = (const float*)d_in[6];
    const float* W_out = (const float*)d_in[7];
    const float* b_out = (const float*)d_in[8];
    float* out = (float*)d_out;

    (void)in_sizes; (void)n_in; (void)out_size;

    int gemm_smem = 2 * STAGE_B + 1024;                       // 66560
    cudaFuncSetAttribute(gemm_k, cudaFuncAttributeMaxDynamicSharedMemorySize, gemm_smem);
    int scan_smem = (4 * VSLC + 128 + 128 + 256 + 128) * 4;   // 134656
    cudaFuncSetAttribute(scan_k, cudaFuncAttributeMaxDynamicSharedMemorySize, scan_smem);

    prep_all_k<<<BN_TOT + NBP, 256>>>(X, W2, b2);
    gemm_k<<<dim3(NBP / BN, BN_TOT / BM), 256, gemm_smem>>>();
    scan_k<<<B_SZ / 2, 256, scan_smem>>>(X, W_in, b_in, W1, b1, W_out, b_out, out);
}

// round 17
// speedup vs baseline: 1.5871x; 1.0205x over previous
#include <cuda_runtime.h>
#include <cuda_fp16.h>
#include <cstdint>

// Problem constants
#define B_SZ   256
#define T_SZ   2049
#define D_SZ   64
#define NI_SZ  128
#define OUT_SZ 10
#define L_SZ   2080
#define S_SZ   16
#define BN_TOT 32768          // GEMM M
#define NBP    8320           // GEMM N: 8192 (W2) + 64 (b2) + 64 zero
#define KD     2080           // GEMM K: 65 iters of 32
#define BM     128
#define BN     128
#define BK     32
#define NKIT   (KD / BK)      // 65
#define STAGE_B 32768         // A 16KB + B 16KB per stage
#define MSP    65             // Ms row stride (bank-conflict-free transpose)

// Scratch (device globals; allocation-free)
__device__ __half g_ls_hi[(size_t)BN_TOT * KD];   // 136 MB
__device__ __half g_ls_lo[(size_t)BN_TOT * KD];   // 136 MB
__device__ __half g_B_hi [(size_t)NBP * KD];      // 34.6 MB
__device__ __half g_B_lo [(size_t)NBP * KD];      // 34.6 MB
__device__ float  g_V    [(size_t)BN_TOT * NBP];  // 1.09 GB

__device__ __forceinline__ void hsplit(float v, __half& h, __half& l) {
    h = __float2half_rn(v);
    l = __float2half_rn(v - __half2float(h));
}
__device__ __forceinline__ void cp16s(uint32_t saddr, const void* g) {
    asm volatile("cp.async.cg.shared.global [%0], [%1], 16;" :: "r"(saddr), "l"(g));
}
// rs(i) = elements in triangle rows [0, i) = 63i - i(i-1)/2
__device__ __forceinline__ int tri_rs(int i) { return 63 * i - ((i * (i - 1)) >> 1); }

// ---------------------------------------------------------------------------
// Kernel 1 (fused): blocks [0, 32768) = logsig for (b, n);
// blocks [32768, 41088) = B rows [W2 flat; b2; zeros].
// ---------------------------------------------------------------------------
__global__ void prep_all_k(const float* __restrict__ X,
                           const float* __restrict__ W2,
                           const float* __restrict__ b2) {
    __shared__ float seg[17 * 64];
    __shared__ float cumS[16 * 64];
    __shared__ float dltS[16 * 64];
    __shared__ float Ms[64 * MSP];

    int t = threadIdx.x;

    if (blockIdx.x >= (unsigned)BN_TOT) {        // ---- prep_B half ----
        int r = blockIdx.x - BN_TOT;
        const float* src = nullptr;
        if (r < 8192)       src = W2 + (size_t)r * L_SZ;
        else if (r < 8256)  src = b2 + (size_t)(r - 8192) * L_SZ;
        size_t o = (size_t)r * KD;
        for (int l = t; l < KD; l += 256) {
            float v = src ? src[l] : 0.0f;
            __half h, lo;
            hsplit(v, h, lo);
            g_B_hi[o + l] = h;
            g_B_lo[o + l] = lo;
        }
        return;
    }

    // ---- logsig half ----
    int n = blockIdx.x & (NI_SZ - 1);
    int b = blockIdx.x >> 7;
    size_t bno = (size_t)(b * NI_SZ + n) * KD;

    const float4* xp4 = (const float4*)(X + ((size_t)b * T_SZ + (size_t)n * S_SZ) * D_SZ);
    float4* seg4 = (float4*)seg;
    for (int i = t; i < 17 * 64 / 4; i += 256) seg4[i] = xp4[i];
    __syncthreads();

    for (int i = t; i < 16 * 64; i += 256) {
        int k = i >> 6, d = i & 63;
        cumS[i] = seg[k * 64 + d] - seg[d];
        dltS[i] = seg[(k + 1) * 64 + d] - seg[k * 64 + d];
    }
    __syncthreads();

    if (t < 64) {
        __half h, lo;
        hsplit(seg[16 * 64 + t] - seg[t], h, lo);
        g_ls_hi[bno + t] = h; g_ls_lo[bno + t] = lo;
    }

    // M[i][j] = sum_k cum[k][i] * dlt[k][j]; thread t owns (i = t>>2, 16 cols)
    {
        int i = t >> 2;
        int jb = (t & 3) * 16;
        float acc[16];
        #pragma unroll
        for (int q = 0; q < 16; ++q) acc[q] = 0.0f;
        #pragma unroll
        for (int k = 0; k < 16; ++k) {
            float ci = cumS[k * 64 + i];
            const float4* dl4 = (const float4*)(dltS + k * 64 + jb);
            #pragma unroll
            for (int q4 = 0; q4 < 4; ++q4) {
                float4 dv = dl4[q4];
                acc[q4 * 4 + 0] += ci * dv.x;
                acc[q4 * 4 + 1] += ci * dv.y;
                acc[q4 * 4 + 2] += ci * dv.z;
                acc[q4 * 4 + 3] += ci * dv.w;
            }
        }
        float* mrow = Ms + i * MSP + jb;
        #pragma unroll
        for (int q = 0; q < 16; ++q) mrow[q] = acc[q];
    }
    __syncthreads();

    // Upper-triangular pairs via closed-form p -> (i, j) with exact fixup.
    for (int p = t; p < 2016; p += 256) {
        int i = (int)(63.5f - sqrtf(4032.25f - 2.0f * (float)p));
        if (i < 0) i = 0;
        while (tri_rs(i + 1) <= p) ++i;   // fixup: at most 1-2 steps
        while (tri_rs(i) > p) --i;
        int j = i + 1 + (p - tri_rs(i));
        float a = 0.5f * (Ms[i * MSP + j] - Ms[j * MSP + i]);
        __half h, lo;
        hsplit(a, h, lo);
        g_ls_hi[bno + 64 + p] = h; g_ls_lo[bno + 64 + p] = lo;
    }
}

// ---------------------------------------------------------------------------
// Kernel 2: TN GEMM  g_V = ls @ B^T, m16n8k16.f16 fp32-acc, 3-product split
// (al*bh + ah*bl + ah*bh). CTA 128x128x32, 8 warps (2x4), warp 64x32,
// 2-stage cp.async with trailing barrier; 2 CTAs/SM. (Round-9 proven body.)
// ---------------------------------------------------------------------------
__device__ __forceinline__ void ldsm4(uint32_t* r, uint32_t addr) {
    asm volatile("ldmatrix.sync.aligned.m8n8.x4.shared.b16 {%0,%1,%2,%3}, [%4];"
                 : "=r"(r[0]), "=r"(r[1]), "=r"(r[2]), "=r"(r[3]) : "r"(addr));
}
__device__ __forceinline__ void mma_f16(float* c, const uint32_t* a, const uint32_t* b) {
    asm volatile(
        "mma.sync.aligned.m16n8k16.row.col.f32.f16.f16.f32 "
        "{%0,%1,%2,%3}, {%4,%5,%6,%7}, {%8,%9}, {%0,%1,%2,%3};"
        : "+f"(c[0]), "+f"(c[1]), "+f"(c[2]), "+f"(c[3])
        : "r"(a[0]), "r"(a[1]), "r"(a[2]), "r"(a[3]), "r"(b[0]), "r"(b[1]));
}

__global__ void __launch_bounds__(256, 2) gemm_k() {
    extern __shared__ uint8_t dsm_raw[];
    uint32_t base0 = (uint32_t)__cvta_generic_to_shared(dsm_raw);
    uint32_t sbase = (base0 + 1023) & ~1023u;

    int tid  = threadIdx.x;
    int lane = tid & 31;
    int wid  = tid >> 5;
    int g    = lane >> 2;
    int tig  = lane & 3;
    int wm   = (wid & 1) * 64;
    int wn   = (wid >> 1) * 32;
    int ntile = blockIdx.x, mtile = blockIdx.y;

    const __half* Agh = g_ls_hi + (size_t)(mtile * BM) * KD;
    const __half* Agl = g_ls_lo + (size_t)(mtile * BM) * KD;
    const __half* Bgh = g_B_hi  + (size_t)(ntile * BN) * KD;
    const __half* Bgl = g_B_lo  + (size_t)(ntile * BN) * KD;

    float c[4][4][4];
    #pragma unroll
    for (int mi = 0; mi < 4; ++mi)
        #pragma unroll
        for (int ni = 0; ni < 4; ++ni)
            #pragma unroll
            for (int q = 0; q < 4; ++q) c[mi][ni][q] = 0.0f;

    // Stage: A 128 rows + B 128 rows, each row 128B = [hi 64B | lo 64B]
    auto stage = [&](int it2, int s) {
        uint32_t base = sbase + (uint32_t)s * STAGE_B;
        int kb = it2 * BK;
        #pragma unroll
        for (int i = 0; i < 8; ++i) {
            int isB   = (i >= 4);
            int local = tid + i * 256 - isB * 1024;
            int row   = local >> 3;
            int ch    = local & 7;
            int hil   = ch >> 2;
            int ck    = ch & 3;
            const __half* src =
                (isB ? (hil ? Bgl : Bgh) + (size_t)row * KD
                     : (hil ? Agl : Agh) + (size_t)row * KD) + kb + ck * 8;
            uint32_t dst = base + (isB ? 16384u : 0u)
                         + (uint32_t)row * 128 + (uint32_t)((ch ^ (row & 7)) << 4);
            cp16s(dst, src);
        }
        asm volatile("cp.async.commit_group;");
    };

    stage(0, 0);

    for (int it = 0; it < NKIT; ++it) {
        int s = it & 1;
        if (it + 1 < NKIT) {
            stage(it + 1, s ^ 1);
            asm volatile("cp.async.wait_group 1;");
        } else {
            asm volatile("cp.async.wait_group 0;");
        }
        __syncthreads();

        uint32_t Ab = sbase + (uint32_t)s * STAGE_B;
        uint32_t Bb = Ab + 16384;

        #pragma unroll
        for (int ks = 0; ks < 2; ++ks) {
            uint32_t ah[4][4], al[4][4], bh[4][2], bl[4][2];
            #pragma unroll
            for (int mi = 0; mi < 4; ++mi) {
                int row = wm + mi * 16 + (lane & 15);
                int kc  = lane >> 4;
                ldsm4(ah[mi], Ab + row * 128 + (((ks * 2 + kc)     ^ (row & 7)) << 4));
                ldsm4(al[mi], Ab + row * 128 + (((4 + ks * 2 + kc) ^ (row & 7)) << 4));
            }
            #pragma unroll
            for (int p = 0; p < 2; ++p) {
                int row = wn + p * 16 + ((lane >> 4) & 1) * 8 + (lane & 7);
                int kc  = (lane >> 3) & 1;
                uint32_t r4[4];
                ldsm4(r4, Bb + row * 128 + (((ks * 2 + kc) ^ (row & 7)) << 4));
                bh[2*p][0] = r4[0]; bh[2*p][1] = r4[1];
                bh[2*p+1][0] = r4[2]; bh[2*p+1][1] = r4[3];
                ldsm4(r4, Bb + row * 128 + (((4 + ks * 2 + kc) ^ (row & 7)) << 4));
                bl[2*p][0] = r4[0]; bl[2*p][1] = r4[1];
                bl[2*p+1][0] = r4[2]; bl[2*p+1][1] = r4[3];
            }
            #pragma unroll
            for (int mi = 0; mi < 4; ++mi)
                #pragma unroll
                for (int ni = 0; ni < 4; ++ni) {
                    mma_f16(c[mi][ni], al[mi], bh[ni]);
                    mma_f16(c[mi][ni], ah[mi], bl[ni]);
                    mma_f16(c[mi][ni], ah[mi], bh[ni]);
                }
        }
        __syncthreads();   // REQUIRED: protects buffer s^1 from next-iter staging
    }

    // Epilogue
    int rowbase = mtile * BM + wm;
    int colbase = ntile * BN + wn;
    #pragma unroll
    for (int mi = 0; mi < 4; ++mi) {
        #pragma unroll
        for (int ni = 0; ni < 4; ++ni) {
            int r0 = rowbase + mi * 16 + g;
            int cc = colbase + ni * 8 + tig * 2;
            *(float2*)&g_V[(size_t)r0 * NBP + cc] =
                make_float2(c[mi][ni][0], c[mi][ni][1]);
            *(float2*)&g_V[(size_t)(r0 + 8) * NBP + cc] =
                make_float2(c[mi][ni][2], c[mi][ni][3]);
        }
    }
}

// ---------------------------------------------------------------------------
// Kernel 3: RK4 scan. 128 CTAs x 256 threads; 2 batch elems per CTA;
// cp.async double-buffered V prefetch; per-half named barriers.
// (Round-9 proven body, 563us.)
// ---------------------------------------------------------------------------
#define VSLC 8256   // 129*64 floats per interval slice

__device__ __forceinline__ void hbar(int half) {
    asm volatile("bar.sync %0, 128;" :: "r"(half + 1) : "memory");
}

__global__ void __launch_bounds__(256) scan_k(
    const float* __restrict__ X,    const float* __restrict__ W_in,
    const float* __restrict__ b_in, const float* __restrict__ W1,
    const float* __restrict__ b1,   const float* __restrict__ W_out,
    const float* __restrict__ b_out, float* __restrict__ out)
{
    extern __shared__ float ssm[];
    float* VsA = ssm;
    float* hA  = ssm + 4 * VSLC;
    float* htA = hA + 128;
    float* zA  = htA + 128;
    float* ksA = zA + 256;

    int half = threadIdx.x >> 7;
    int t    = threadIdx.x & 127;
    int b    = blockIdx.x * 2 + half;

    float* h    = hA  + half * 64;
    float* ht   = htA + half * 64;
    float* z    = zA  + half * 128;
    float* ksum = ksA + half * 64;

    float w1r[64];
    #pragma unroll
    for (int i = 0; i < 64; ++i) w1r[i] = W1[i * 128 + t];
    float b1t = b1[t];

    if (t < 64) {
        float acc = b_in[t];
        const float* x0 = X + (size_t)b * T_SZ * D_SZ;
        #pragma unroll
        for (int d = 0; d < 64; ++d) acc += x0[d] * W_in[d * 64 + t];
        h[t] = acc; ht[t] = acc; ksum[t] = 0.0f;
    }

    uint32_t vs_s[2];
    vs_s[0] = (uint32_t)__cvta_generic_to_shared(VsA + (half * 2 + 0) * VSLC);
    vs_s[1] = (uint32_t)__cvta_generic_to_shared(VsA + (half * 2 + 1) * VSLC);

    auto prefetch = [&](int n, int buf) {
        const float* vg = g_V + (size_t)(b * NI_SZ + n) * NBP;
        uint32_t dst = vs_s[buf];
        for (int c4 = t; c4 < VSLC / 4; c4 += 128)
            cp16s(dst + c4 * 16, vg + c4 * 4);
        asm volatile("cp.async.commit_group;");
    };

    prefetch(0, 0);

    const float wgt[4] = {1.0f, 2.0f, 2.0f, 1.0f};
    const float aco[4] = {0.5f, 0.5f, 1.0f, 0.0f};

    for (int n = 0; n < NI_SZ; ++n) {
        asm volatile("cp.async.wait_group 0;");
        hbar(half);
        if (n + 1 < NI_SZ) prefetch(n + 1, (n + 1) & 1);
        const float* Vs = VsA + (half * 2 + (n & 1)) * VSLC;

        #pragma unroll
        for (int s = 0; s < 4; ++s) {
            float a0 = b1t, a1 = 0.0f, a2 = 0.0f, a3 = 0.0f;
            #pragma unroll
            for (int i = 0; i < 64; i += 4) {
                a0 += ht[i]     * w1r[i];
                a1 += ht[i + 1] * w1r[i + 1];
                a2 += ht[i + 2] * w1r[i + 2];
                a3 += ht[i + 3] * w1r[i + 3];
            }
            z[t] = tanhf((a0 + a1) + (a2 + a3));
            hbar(half);
            if (t < 64) {
                float k0 = Vs[128 * 64 + t], k1 = 0.0f, k2 = 0.0f, k3 = 0.0f;
                #pragma unroll
                for (int m = 0; m < 128; m += 4) {
                    k0 += z[m]     * Vs[m * 64 + t];
                    k1 += z[m + 1] * Vs[(m + 1) * 64 + t];
                    k2 += z[m + 2] * Vs[(m + 2) * 64 + t];
                    k3 += z[m + 3] * Vs[(m + 3) * 64 + t];
                }
                float ka = (k0 + k1) + (k2 + k3);
                ksum[t] += wgt[s] * ka;
                if (s < 3) ht[t] = h[t] + aco[s] * ka;
            }
            hbar(half);
        }
        if (t < 64) {
            float hn = h[t] + ksum[t] * (1.0f / 6.0f);
            h[t] = hn; ht[t] = hn; ksum[t] = 0.0f;
        }
    }

    if (t < OUT_SZ) {
        float acc = b_out[t];
        #pragma unroll
        for (int d = 0; d < 64; ++d) acc += h[d] * W_out[d * OUT_SZ + t];
        out[b * OUT_SZ + t] = acc;
    }
}

// ---------------------------------------------------------------------------
extern "C" void kernel_launch(void* const* d_in, const int* in_sizes, int n_in,
                              void* d_out, int out_size) {
    const float* X     = (const float*)d_in[0];
    const float* W_in  = (const float*)d_in[1];
    const float* b_in  = (const float*)d_in[2];
    const float* W1    = (const float*)d_in[3];
    const float* b1    = (const float*)d_in[4];
    const float* W2    = (const float*)d_in[5];
    const float* b2    = (const float*)d_in[6];
    const float* W_out = (const float*)d_in[7];
    const float* b_out = (const float*)d_in[8];
    float* out = (float*)d_out;

    (void)in_sizes; (void)n_in; (void)out_size;

    int gemm_smem = 2 * STAGE_B + 1024;                       // 66560
    cudaFuncSetAttribute(gemm_k, cudaFuncAttributeMaxDynamicSharedMemorySize, gemm_smem);
    int scan_smem = (4 * VSLC + 128 + 128 + 256 + 128) * 4;   // 134656
    cudaFuncSetAttribute(scan_k, cudaFuncAttributeMaxDynamicSharedMemorySize, scan_smem);

    prep_all_k<<<BN_TOT + NBP, 256>>>(X, W2, b2);
    gemm_k<<<dim3(NBP / BN, BN_TOT / BM), 256, gemm_smem>>>();
    scan_k<<<B_SZ / 2, 256, scan_smem>>>(X, W_in, b_in, W1, b1, W_out, b_out, out);
}